// round 2
// baseline (speedup 1.0000x reference)
#include <cuda_runtime.h>

#define BB 8
#define PP 12000
#define MM 32
#define FF 9
#define CC 64
#define XN_ 144
#define CELLS (144*144)

// per-(batch,cell) winning pillar index (last write wins == max p)
__device__ int g_winner[BB * CELLS];

__global__ void k_init_winner() {
    int i = blockIdx.x * blockDim.x + threadIdx.x;
    if (i < BB * CELLS) g_winner[i] = -1;
}

__global__ void k_winner(const int* __restrict__ idx) {
    int i = blockIdx.x * blockDim.x + threadIdx.x;
    if (i >= BB * PP) return;
    int y = idx[i * 3 + 1];
    int x = idx[i * 3 + 2];
    x = x < 0 ? 0 : (x > 143 ? 143 : x);
    y = y < 0 ? 0 : (y > 143 ? 143 : y);   // data guarantees in-range; defensive only
    int b = i / PP;
    int p = i - b * PP;
    int flat = y * XN_ + x;
    atomicMax(&g_winner[b * CELLS + flat], p);
}

__device__ __forceinline__ unsigned long long fma2(unsigned long long a,
                                                   unsigned long long b,
                                                   unsigned long long c) {
    unsigned long long d;
    asm("fma.rn.f32x2 %0, %1, %2, %3;" : "=l"(d) : "l"(a), "l"(b), "l"(c));
    return d;
}
__device__ __forceinline__ unsigned long long splat2(float s) {
    unsigned long long d;
    asm("mov.b64 %0, {%1, %1};" : "=l"(d) : "f"(s));
    return d;
}
__device__ __forceinline__ void unpack2(unsigned long long v, float& lo, float& hi) {
    asm("mov.b64 {%0, %1}, %2;" : "=f"(lo), "=f"(hi) : "l"(v));
}

// One warp per pillar. Thread = channel pair (c, c+32).
// Pillar tile transposed in smem as [f][m] so LDS.128 yields 4 consecutive
// m-values = two packed f32x2 operands, no pack instructions in the hot loop.
__global__ void __launch_bounds__(256) k_compute(
    const float* __restrict__ pillars,
    const int* __restrict__ idx,
    const float* __restrict__ cw,
    const float* __restrict__ gamma,
    const float* __restrict__ beta,
    const float* __restrict__ mean,
    const float* __restrict__ var,
    float* __restrict__ out)
{
    __shared__ __align__(16) float sm[8][FF * MM];   // 8 pillars per 256-thr block
    int wlocal = threadIdx.x >> 5;
    int lane   = threadIdx.x & 31;
    int u = blockIdx.x * 8 + wlocal;                 // global pillar id
    if (u >= BB * PP) return;
    int b = u / PP;
    int p = u - b * PP;

    int y  = idx[u * 3 + 1];
    int xx = idx[u * 3 + 2];
    xx = xx < 0 ? 0 : (xx > 143 ? 143 : xx);
    y  = y  < 0 ? 0 : (y  > 143 ? 143 : y);
    int flat = y * XN_ + xx;
    if (g_winner[b * CELLS + flat] != p) return;     // loser pillar: no work

    // Coalesced load of the 288-float pillar, transposed into smem [f][m]
    const float* src = pillars + (long long)u * (MM * FF);
    float* smp = sm[wlocal];
    #pragma unroll
    for (int k = 0; k < 9; k++) {
        int i = lane + k * 32;
        float v = src[i];
        int m = i / 9;
        int f = i - m * 9;
        smp[f * 32 + m] = v;
    }
    __syncwarp();

    int c = lane;
    unsigned long long wa[9], wb[9];
    #pragma unroll
    for (int f = 0; f < 9; f++) {
        wa[f] = splat2(cw[c * 9 + f]);
        wb[f] = splat2(cw[(c + 32) * 9 + f]);
    }

    float mA = -3.402823466e38f, mB = -3.402823466e38f;
    #pragma unroll
    for (int q = 0; q < 8; q++) {   // m-quads: m = 4q .. 4q+3
        unsigned long long a0 = 0ull, a1 = 0ull, b0 = 0ull, b1 = 0ull;
        #pragma unroll
        for (int f = 0; f < 9; f++) {
            ulonglong2 v = *reinterpret_cast<const ulonglong2*>(smp + f * 32 + q * 4);
            a0 = fma2(v.x, wa[f], a0);
            a1 = fma2(v.y, wa[f], a1);
            b0 = fma2(v.x, wb[f], b0);
            b1 = fma2(v.y, wb[f], b1);
        }
        float t0, t1, t2, t3;
        unpack2(a0, t0, t1); unpack2(a1, t2, t3);
        mA = fmaxf(mA, fmaxf(fmaxf(t0, t1), fmaxf(t2, t3)));
        unpack2(b0, t0, t1); unpack2(b1, t2, t3);
        mB = fmaxf(mB, fmaxf(fmaxf(t0, t1), fmaxf(t2, t3)));
    }

    // BN scale > 0 and ReLU monotone => affine+relu applied once to the raw max
    float sA = gamma[c]      * rsqrtf(var[c]      + 1e-5f);
    float sB = gamma[c + 32] * rsqrtf(var[c + 32] + 1e-5f);
    float fA = fmaxf((mA - mean[c])      * sA + beta[c],      0.0f);
    float fB = fmaxf((mB - mean[c + 32]) * sB + beta[c + 32], 0.0f);

    out[((long long)(b * CC + c))      * CELLS + flat] = fA;
    out[((long long)(b * CC + c + 32)) * CELLS + flat] = fB;
}

extern "C" void kernel_launch(void* const* d_in, const int* in_sizes, int n_in,
                              void* d_out, int out_size) {
    const float* pillars = (const float*)d_in[0];
    const int*   idx     = (const int*)d_in[1];
    const float* cw      = (const float*)d_in[2];
    const float* gamma   = (const float*)d_in[3];
    const float* beta    = (const float*)d_in[4];
    const float* mean    = (const float*)d_in[5];
    const float* var     = (const float*)d_in[6];
    float* out = (float*)d_out;

    cudaMemsetAsync(out, 0, (size_t)out_size * sizeof(float), 0);
    k_init_winner<<<(BB * CELLS + 255) / 256, 256>>>();
    k_winner<<<(BB * PP + 255) / 256, 256>>>(idx);
    k_compute<<<(BB * PP) / 8, 256>>>(pillars, idx, cw, gamma, beta, mean, var, out);
}

// round 3
// speedup vs baseline: 1.1904x; 1.1904x over previous
#include <cuda_runtime.h>

#define BB 8
#define PP 12000
#define NP (BB*PP)
#define XN_ 144
#define CELLS (144*144)

// per-(batch,cell) winning pillar index (last write wins == max p)
__device__ int g_winner[BB * CELLS];

__global__ void k_winner(const int* __restrict__ idx) {
    int i = blockIdx.x * blockDim.x + threadIdx.x;
    if (i >= NP) return;
    int y = idx[i * 3 + 1];
    int x = idx[i * 3 + 2];
    x = min(max(x, 0), 143);
    y = min(max(y, 0), 143);
    int b = i / PP;
    int p = i - b * PP;
    atomicMax(&g_winner[b * CELLS + y * XN_ + x], p);
}

__device__ __forceinline__ unsigned long long fma2(unsigned long long a,
                                                   unsigned long long b,
                                                   unsigned long long c) {
    unsigned long long d;
    asm("fma.rn.f32x2 %0, %1, %2, %3;" : "=l"(d) : "l"(a), "l"(b), "l"(c));
    return d;
}
__device__ __forceinline__ unsigned long long splat2(float s) {
    unsigned long long d;
    asm("mov.b64 %0, {%1, %1};" : "=l"(d) : "f"(s));
    return d;
}
__device__ __forceinline__ void unpack2(unsigned long long v, float& lo, float& hi) {
    asm("mov.b64 {%0, %1}, %2;" : "=f"(lo), "=f"(hi) : "l"(v));
}

// Persistent kernel. One warp processes pillars in a grid-stride loop.
// Thread = channel pair (c, c+32); weights + folded BN constants live in
// registers for the whole kernel. Pillar tile transposed in smem as
// [f][36] (pad 36: STS conflicts <=2-way, LDS.128 stays 16B-aligned).
__global__ void __launch_bounds__(256, 3) k_compute(
    const float* __restrict__ pillars,
    const int* __restrict__ idx,
    const float* __restrict__ cw,
    const float* __restrict__ gamma,
    const float* __restrict__ beta,
    const float* __restrict__ mean,
    const float* __restrict__ var,
    float* __restrict__ out)
{
    __shared__ __align__(16) float sm[8][9 * 36];
    const int wlocal = threadIdx.x >> 5;
    const int lane   = threadIdx.x & 31;
    float* smp = sm[wlocal];
    const int c = lane;

    // Per-warp constants: packed weights + folded BN affine (loaded once).
    unsigned long long wa[9], wb[9];
    #pragma unroll
    for (int f = 0; f < 9; f++) {
        wa[f] = splat2(cw[c * 9 + f]);
        wb[f] = splat2(cw[(c + 32) * 9 + f]);
    }
    const float sA = gamma[c]      * rsqrtf(var[c]      + 1e-5f);
    const float sB = gamma[c + 32] * rsqrtf(var[c + 32] + 1e-5f);
    const float bA = beta[c]      - mean[c]      * sA;
    const float bB = beta[c + 32] - mean[c + 32] * sB;

    const int totalWarps = (gridDim.x * blockDim.x) >> 5;
    const int w0 = (blockIdx.x * blockDim.x + threadIdx.x) >> 5;

    for (int u = w0; u < NP; u += totalWarps) {
        int y  = idx[u * 3 + 1];
        int xx = idx[u * 3 + 2];
        xx = min(max(xx, 0), 143);
        y  = min(max(y, 0), 143);
        const int b = u / PP;
        const int p = u - b * PP;
        const int flat = y * XN_ + xx;
        if (g_winner[b * CELLS + flat] != p) continue;   // loser: skip all work

        // Coalesced 288-float load, transposed into smem [f][36]
        const float* src = pillars + (size_t)u * 288;
        #pragma unroll
        for (int k = 0; k < 9; k++) {
            int i = lane + k * 32;
            float v = src[i];
            int m = i / 9;
            int f = i - m * 9;
            smp[f * 36 + m] = v;
        }
        __syncwarp();

        float mA = -3.402823466e38f, mB = -3.402823466e38f;
        #pragma unroll
        for (int q = 0; q < 8; q++) {   // m-quads: m = 4q .. 4q+3
            unsigned long long a0 = 0ull, a1 = 0ull, b0 = 0ull, b1 = 0ull;
            #pragma unroll
            for (int f = 0; f < 9; f++) {
                ulonglong2 v = *reinterpret_cast<const ulonglong2*>(smp + f * 36 + q * 4);
                a0 = fma2(v.x, wa[f], a0);
                a1 = fma2(v.y, wa[f], a1);
                b0 = fma2(v.x, wb[f], b0);
                b1 = fma2(v.y, wb[f], b1);
            }
            float t0, t1, t2, t3;
            unpack2(a0, t0, t1); unpack2(a1, t2, t3);
            mA = fmaxf(mA, fmaxf(fmaxf(t0, t1), fmaxf(t2, t3)));
            unpack2(b0, t0, t1); unpack2(b1, t2, t3);
            mB = fmaxf(mB, fmaxf(fmaxf(t0, t1), fmaxf(t2, t3)));
        }
        __syncwarp();   // all lanes done reading smem before next iter's STS

        // BN scale > 0 and ReLU monotone => affine+relu once on the raw max
        const float fA = fmaxf(fmaf(mA, sA, bA), 0.0f);
        const float fB = fmaxf(fmaf(mB, sB, bB), 0.0f);

        const size_t base = ((size_t)(b * 64 + c)) * CELLS + flat;
        out[base]              = fA;
        out[base + 32 * CELLS] = fB;
    }
}

extern "C" void kernel_launch(void* const* d_in, const int* in_sizes, int n_in,
                              void* d_out, int out_size) {
    const float* pillars = (const float*)d_in[0];
    const int*   idx     = (const int*)d_in[1];
    const float* cw      = (const float*)d_in[2];
    const float* gamma   = (const float*)d_in[3];
    const float* beta    = (const float*)d_in[4];
    const float* mean    = (const float*)d_in[5];
    const float* var     = (const float*)d_in[6];
    float* out = (float*)d_out;

    void* winner_ptr = nullptr;
    cudaGetSymbolAddress(&winner_ptr, g_winner);

    cudaMemsetAsync(out, 0, (size_t)out_size * sizeof(float), 0);
    cudaMemsetAsync(winner_ptr, 0xFF, sizeof(int) * BB * CELLS, 0);  // -1
    k_winner<<<(NP + 255) / 256, 256>>>(idx);
    k_compute<<<456, 256>>>(pillars, idx, cw, gamma, beta, mean, var, out);
}